// round 2
// baseline (speedup 1.0000x reference)
#include <cuda_runtime.h>
#include <cuda_bf16.h>

// Inputs (metadata order):
//  d_in[0] charges             float32 [200000, 4]
//  d_in[1] cell                float32 [3, 3]        (unused)
//  d_in[2] positions           float32 [200000, 3]   (unused)
//  d_in[3] neighbor_indices    int32   [12800000, 2]
//  d_in[4] neighbor_distances  float32 [12800000]
//  d_out  potential            float32 [200000, 4]
//
// out[i] += 0.5/d * charges[j];  out[j] += 0.5/d * charges[i]  over all edges.
//
// R2: 4 edges/thread. Stream loads vectorized (2x int4 + 1x float4, streaming
// hint), 8 gathers issued back-to-back for MLP, then 8 red.global.add.v4.f32.

__device__ __forceinline__ void red_add_v4(float4* p, float4 v) {
    asm volatile("red.global.add.v4.f32 [%0], {%1, %2, %3, %4};"
                 :: "l"(p), "f"(v.x), "f"(v.y), "f"(v.z), "f"(v.w)
                 : "memory");
}

__device__ __forceinline__ float4 scale4(float4 c, float w) {
    return make_float4(c.x * w, c.y * w, c.z * w, c.w * w);
}

__global__ void __launch_bounds__(256)
edge_scatter_kernel(const float4* __restrict__ charges,
                    const int4*   __restrict__ nbr4,    // 2 edges per int4
                    const float4* __restrict__ dist4,   // 4 edges per float4
                    const int2*   __restrict__ nbr,     // scalar view for tail
                    const float*  __restrict__ dist,
                    float4*       __restrict__ out,
                    int n_edges) {
    int t  = blockIdx.x * blockDim.x + threadIdx.x;
    int e0 = t * 4;

    if (e0 + 3 < n_edges) {
        int4   ab = __ldcs(&nbr4[2 * t]);       // edges e0, e0+1: (i0,j0,i1,j1)
        int4   cd = __ldcs(&nbr4[2 * t + 1]);   // edges e0+2, e0+3
        float4 dd = __ldcs(&dist4[t]);

        float w0 = 0.5f / dd.x;
        float w1 = 0.5f / dd.y;
        float w2 = 0.5f / dd.z;
        float w3 = 0.5f / dd.w;

        // 8 independent gathers — maximize MLP before any RED.
        float4 ci0 = __ldg(&charges[ab.x]);
        float4 cj0 = __ldg(&charges[ab.y]);
        float4 ci1 = __ldg(&charges[ab.z]);
        float4 cj1 = __ldg(&charges[ab.w]);
        float4 ci2 = __ldg(&charges[cd.x]);
        float4 cj2 = __ldg(&charges[cd.y]);
        float4 ci3 = __ldg(&charges[cd.z]);
        float4 cj3 = __ldg(&charges[cd.w]);

        red_add_v4(&out[ab.x], scale4(cj0, w0));
        red_add_v4(&out[ab.y], scale4(ci0, w0));
        red_add_v4(&out[ab.z], scale4(cj1, w1));
        red_add_v4(&out[ab.w], scale4(ci1, w1));
        red_add_v4(&out[cd.x], scale4(cj2, w2));
        red_add_v4(&out[cd.y], scale4(ci2, w2));
        red_add_v4(&out[cd.z], scale4(cj3, w3));
        red_add_v4(&out[cd.w], scale4(ci3, w3));
    } else if (e0 < n_edges) {
        for (int e = e0; e < n_edges; ++e) {
            int2  ij = __ldg(&nbr[e]);
            float w  = 0.5f / __ldg(&dist[e]);
            float4 cj = __ldg(&charges[ij.y]);
            float4 ci = __ldg(&charges[ij.x]);
            red_add_v4(&out[ij.x], scale4(cj, w));
            red_add_v4(&out[ij.y], scale4(ci, w));
        }
    }
}

extern "C" void kernel_launch(void* const* d_in, const int* in_sizes, int n_in,
                              void* d_out, int out_size) {
    const float4* charges = (const float4*)d_in[0];
    const int4*   nbr4    = (const int4*)d_in[3];
    const int2*   nbr     = (const int2*)d_in[3];
    const float4* dist4   = (const float4*)d_in[4];
    const float*  dist    = (const float*)d_in[4];
    float4*       out     = (float4*)d_out;

    int n_edges = in_sizes[4];  // 12,800,000

    cudaMemsetAsync(d_out, 0, (size_t)out_size * sizeof(float));

    const int TPB = 256;
    int threads_needed = (n_edges + 3) / 4;
    int blocks = (threads_needed + TPB - 1) / TPB;
    edge_scatter_kernel<<<blocks, TPB>>>(charges, nbr4, dist4, nbr, dist, out, n_edges);
}